// round 3
// baseline (speedup 1.0000x reference)
#include <cuda_runtime.h>

#define TLEN 2048
#define NBMAX 4096

// Scratch for [h_f | h_b] per batch element: [B][18]
__device__ float g_y[NBMAX * 18];

__device__ __forceinline__ float ftanh(float v) {
    // tanh(x) = (e^{2x}-1)/(e^{2x}+1); clamp to avoid inf/inf. abs err ~1e-7.
    float x = fminf(fmaxf(v, -15.f), 15.f);
    float e = __expf(2.f * x);
    return __fdividef(e - 1.f, e + 1.f);
}

// ---------------------------------------------------------------------------
// Phase 1: bidirectional Elman RNN (H1=9, D_IN=5), final hidden only.
// 2 lanes per sequence: lane group g in {0,1} owns hidden units g*5..g*5+4
// (unit 9 is a zero-weight pad). 16 sequences per warp. One warp per block.
// Weights are register-resident, with Whh columns pre-permuted into
// (own-group values, other-group values) order so no selects are needed.
// ---------------------------------------------------------------------------
__global__ __launch_bounds__(32) void rnn1_kernel(
    const float* __restrict__ x,
    const float* __restrict__ wih_f, const float* __restrict__ whh_f,
    const float* __restrict__ bih_f, const float* __restrict__ bhh_f,
    const float* __restrict__ wih_b, const float* __restrict__ whh_b,
    const float* __restrict__ bih_b, const float* __restrict__ bhh_b)
{
    const int lane = threadIdx.x;
    const int g = lane >> 4;          // unit-group: 0 -> units 0..4, 1 -> 5..8(+pad)
    const int r = lane & 15;          // sequence slot within warp
    const int w = blockIdx.x;
    const int wpd = gridDim.x >> 1;   // warps per direction
    const int dir = (w >= wpd) ? 1 : 0;
    const int b = (dir ? (w - wpd) : w) * 16 + r;

    const float* Wih = dir ? wih_b : wih_f;
    const float* Whh = dir ? whh_b : whh_f;
    const float* Bi  = dir ? bih_b : bih_f;
    const float* Bh  = dir ? bhh_b : bhh_f;

    float wih[5][5];     // input weights for my 5 units
    float whA[5][5];     // Whh coeffs against my own group's values
    float whB[5][5];     // Whh coeffs against the other group's values
    float bias[5];

#pragma unroll
    for (int k = 0; k < 5; k++) {
        const int u = g * 5 + k;
        const bool uv = (u < 9);
#pragma unroll
        for (int j = 0; j < 5; j++)
            wih[k][j] = uv ? Wih[u * 5 + j] : 0.f;
#pragma unroll
        for (int c = 0; c < 5; c++) {
            const int colA = g ? (5 + c) : c;   // column fed by my group's value c
            const int colB = g ? c : (5 + c);   // column fed by other group's value c
            whA[k][c] = (uv && colA < 9) ? Whh[u * 9 + colA] : 0.f;
            whB[k][c] = (uv && colB < 9) ? Whh[u * 9 + colB] : 0.f;
        }
        bias[k] = uv ? (Bi[u] + Bh[u]) : 0.f;
    }

    // loop-carried state: my group's 5 values + other group's 5 values
    float mh[5], oh[5];
#pragma unroll
    for (int k = 0; k < 5; k++) { mh[k] = 0.f; oh[k] = 0.f; }

    const int stride = dir ? -5 : 5;
    const float* xp = x + ((long)b * TLEN + (dir ? (TLEN - 1) : 0)) * 5;

    float xa[5], xb[5];
#pragma unroll
    for (int j = 0; j < 5; j++) xa[j] = xp[j];
    xp += stride;
#pragma unroll
    for (int j = 0; j < 5; j++) xb[j] = xp[j];
    xp += stride;

    for (int t = 0; t < TLEN; t += 2) {
        // distance-2 prefetch (branchless: clamp the tail loads to a safe addr)
        float xn0[5], xn1[5];
        const float* p0 = (t + 2 < TLEN) ? xp : x;
        const float* p1 = (t + 3 < TLEN) ? (xp + stride) : x;
#pragma unroll
        for (int j = 0; j < 5; j++) xn0[j] = p0[j];
#pragma unroll
        for (int j = 0; j < 5; j++) xn1[j] = p1[j];
        xp += 2 * stride;

        // ---- step with xa ----
        {
            float nh[5];
#pragma unroll
            for (int k = 0; k < 5; k++) {
                float a = bias[k];
#pragma unroll
                for (int j = 0; j < 5; j++) a = fmaf(xa[j], wih[k][j], a);
#pragma unroll
                for (int c = 0; c < 5; c++) a = fmaf(mh[c], whA[k][c], a);
#pragma unroll
                for (int c = 0; c < 5; c++) a = fmaf(oh[c], whB[k][c], a);
                nh[k] = ftanh(a);
            }
#pragma unroll
            for (int k = 0; k < 5; k++) {
                oh[k] = __shfl_xor_sync(0xffffffffu, nh[k], 16);
                mh[k] = nh[k];
            }
        }
        // ---- step with xb ----
        {
            float nh[5];
#pragma unroll
            for (int k = 0; k < 5; k++) {
                float a = bias[k];
#pragma unroll
                for (int j = 0; j < 5; j++) a = fmaf(xb[j], wih[k][j], a);
#pragma unroll
                for (int c = 0; c < 5; c++) a = fmaf(mh[c], whA[k][c], a);
#pragma unroll
                for (int c = 0; c < 5; c++) a = fmaf(oh[c], whB[k][c], a);
                nh[k] = ftanh(a);
            }
#pragma unroll
            for (int k = 0; k < 5; k++) {
                oh[k] = __shfl_xor_sync(0xffffffffu, nh[k], 16);
                mh[k] = nh[k];
            }
        }

#pragma unroll
        for (int j = 0; j < 5; j++) { xa[j] = xn0[j]; xb[j] = xn1[j]; }
    }

    // write my final units: y[b][dir*9 + u]
#pragma unroll
    for (int k = 0; k < 5; k++) {
        const int u = g * 5 + k;
        if (u < 9) g_y[b * 18 + dir * 9 + u] = mh[k];
    }
}

// ---------------------------------------------------------------------------
// Phase 2: 25-step RNN (H2=32) with input only at t=0, + 32->3 projection.
// One warp per batch element; lane = hidden unit; shfl-broadcast GEMV.
// ---------------------------------------------------------------------------
__global__ __launch_bounds__(128) void rnn2_kernel(
    const float* __restrict__ wih2, const float* __restrict__ whh2,
    const float* __restrict__ bih2, const float* __restrict__ bhh2,
    const float* __restrict__ wout, const float* __restrict__ bout,
    float* __restrict__ out, int B)
{
    const int warp = (blockIdx.x * blockDim.x + threadIdx.x) >> 5;
    const int lane = threadIdx.x & 31;
    if (warp >= B) return;
    const int b = warp;

    float wh[32];
#pragma unroll
    for (int j = 0; j < 32; j++) wh[j] = whh2[lane * 32 + j];
    float wi[18];
#pragma unroll
    for (int j = 0; j < 18; j++) wi[j] = wih2[lane * 18 + j];
    const float bias = bih2[lane] + bhh2[lane];
    const float wo0 = wout[lane], wo1 = wout[32 + lane], wo2 = wout[64 + lane];
    const float bo0 = bout[0], bo1 = bout[1], bo2 = bout[2];

    const float yv = (lane < 18) ? g_y[b * 18 + lane] : 0.f;
    float pre = bias;
#pragma unroll
    for (int j = 0; j < 18; j++)
        pre = fmaf(__shfl_sync(0xffffffffu, yv, j), wi[j], pre);
    float h = ftanh(pre);

    float* ob = out + (long)b * 75;
    for (int t = 0; t < 25; t++) {
        float s0 = h * wo0, s1 = h * wo1, s2 = h * wo2;
#pragma unroll
        for (int o = 16; o > 0; o >>= 1) {
            s0 += __shfl_xor_sync(0xffffffffu, s0, o);
            s1 += __shfl_xor_sync(0xffffffffu, s1, o);
            s2 += __shfl_xor_sync(0xffffffffu, s2, o);
        }
        if (lane == 0) {
            ob[t * 3 + 0] = s0 + bo0;
            ob[t * 3 + 1] = s1 + bo1;
            ob[t * 3 + 2] = s2 + bo2;
        }
        if (t < 24) {
            float p = bias;
#pragma unroll
            for (int j = 0; j < 32; j++)
                p = fmaf(__shfl_sync(0xffffffffu, h, j), wh[j], p);
            h = ftanh(p);
        }
    }
}

extern "C" void kernel_launch(void* const* d_in, const int* in_sizes, int n_in,
                              void* d_out, int out_size)
{
    const float* x      = (const float*)d_in[0];
    const float* wih_f  = (const float*)d_in[1];
    const float* whh_f  = (const float*)d_in[2];
    const float* bih_f  = (const float*)d_in[3];
    const float* bhh_f  = (const float*)d_in[4];
    const float* wih_b  = (const float*)d_in[5];
    const float* whh_b  = (const float*)d_in[6];
    const float* bih_b  = (const float*)d_in[7];
    const float* bhh_b  = (const float*)d_in[8];
    const float* wih2   = (const float*)d_in[9];
    const float* whh2   = (const float*)d_in[10];
    const float* bih2   = (const float*)d_in[11];
    const float* bhh2   = (const float*)d_in[12];
    const float* wout   = (const float*)d_in[13];
    const float* bout   = (const float*)d_in[14];
    float* out = (float*)d_out;

    const int B = in_sizes[0] / (TLEN * 5);      // 4096
    const int warps1 = (2 * B) / 16;             // 512 warps (one per block)
    rnn1_kernel<<<warps1, 32>>>(x, wih_f, whh_f, bih_f, bhh_f,
                                wih_b, whh_b, bih_b, bhh_b);

    const int blocks2 = (B + 3) / 4;             // 4 warps per block
    rnn2_kernel<<<blocks2, 128>>>(wih2, whh2, bih2, bhh2, wout, bout, out, B);
}

// round 5
// speedup vs baseline: 1.0830x; 1.0830x over previous
#include <cuda_runtime.h>

#define TLEN 2048
#define NBMAX 4096

// Scratch for [h_f | h_b] per batch element: [B][18]
__device__ float g_y[NBMAX * 18];

// Fast HW tanh (MUFU.TANH). Saturates correctly for all finite inputs.
__device__ __forceinline__ float ftanh_fast(float x) {
    float y;
    asm("tanh.approx.f32 %0, %1;" : "=f"(y) : "f"(x));
    return y;
}

// Exact-ish tanh, clamp-free: 1 - 2/(e^{2x}+1).  x->+inf: 1-0=1; x->-inf: 1-2=-1.
__device__ __forceinline__ float ftanh_exact(float x) {
    float e = __expf(2.f * x);
    return fmaf(-2.f, __frcp_rn(e + 1.f), 1.f);
}

// ---------------------------------------------------------------------------
// Phase 1: bidirectional Elman RNN (H1=9, D_IN=5), final hidden only.
// 2 lane-groups per sequence (units 0..4 / 5..8+pad), 16 seqs per warp.
// 4 warps per block -> warps pinned to SMSPs 0..3 (1 warp/SMSP everywhere).
// ---------------------------------------------------------------------------
__global__ __launch_bounds__(128) void rnn1_kernel(
    const float* __restrict__ x,
    const float* __restrict__ wih_f, const float* __restrict__ whh_f,
    const float* __restrict__ bih_f, const float* __restrict__ bhh_f,
    const float* __restrict__ wih_b, const float* __restrict__ whh_b,
    const float* __restrict__ bih_b, const float* __restrict__ bhh_b)
{
    const int lane = threadIdx.x & 31;
    const int g = lane >> 4;          // unit-group: 0 -> units 0..4, 1 -> 5..8(+pad)
    const int r = lane & 15;          // sequence slot within warp
    const int w = blockIdx.x * 4 + (threadIdx.x >> 5);   // global warp id, 0..511
    const int wpd = 256;              // warps per direction (4096/16)
    const int dir = (w >= wpd) ? 1 : 0;
    const int b = (dir ? (w - wpd) : w) * 16 + r;

    const float* Wih = dir ? wih_b : wih_f;
    const float* Whh = dir ? whh_b : whh_f;
    const float* Bi  = dir ? bih_b : bih_f;
    const float* Bh  = dir ? bhh_b : bhh_f;

    float wih[5][5];     // input weights for my 5 units
    float whA[5][5];     // Whh coeffs against my own group's values
    float whB[5][5];     // Whh coeffs against the other group's values
    float bias[5];

#pragma unroll
    for (int k = 0; k < 5; k++) {
        const int u = g * 5 + k;
        const bool uv = (u < 9);
#pragma unroll
        for (int j = 0; j < 5; j++)
            wih[k][j] = uv ? Wih[u * 5 + j] : 0.f;
#pragma unroll
        for (int c = 0; c < 5; c++) {
            const int colA = g ? (5 + c) : c;   // column fed by my group's value c
            const int colB = g ? c : (5 + c);   // column fed by other group's value c
            whA[k][c] = (uv && colA < 9) ? Whh[u * 9 + colA] : 0.f;
            whB[k][c] = (uv && colB < 9) ? Whh[u * 9 + colB] : 0.f;
        }
        bias[k] = uv ? (Bi[u] + Bh[u]) : 0.f;
    }

    // loop-carried state: my group's 5 values + other group's 5 values
    float mh[5], oh[5];
#pragma unroll
    for (int k = 0; k < 5; k++) { mh[k] = 0.f; oh[k] = 0.f; }

    const int stride = dir ? -5 : 5;
    const float* xp = x + ((long)b * TLEN + (dir ? (TLEN - 1) : 0)) * 5;

    float xa[5], xb[5];
#pragma unroll
    for (int j = 0; j < 5; j++) xa[j] = xp[j];
    xp += stride;
#pragma unroll
    for (int j = 0; j < 5; j++) xb[j] = xp[j];
    xp += stride;

    for (int t = 0; t < TLEN; t += 2) {
        // distance-2 prefetch (branchless: clamp the tail loads to a safe addr)
        float xn0[5], xn1[5];
        const float* p0 = (t + 2 < TLEN) ? xp : x;
        const float* p1 = (t + 3 < TLEN) ? (xp + stride) : x;
#pragma unroll
        for (int j = 0; j < 5; j++) xn0[j] = p0[j];
#pragma unroll
        for (int j = 0; j < 5; j++) xn1[j] = p1[j];
        xp += 2 * stride;

        // ---- step with xa ----
        {
            float nh[5];
#pragma unroll
            for (int k = 0; k < 5; k++) {
                float a = bias[k];
#pragma unroll
                for (int j = 0; j < 5; j++) a = fmaf(xa[j], wih[k][j], a);
#pragma unroll
                for (int c = 0; c < 5; c++) a = fmaf(mh[c], whA[k][c], a);
#pragma unroll
                for (int c = 0; c < 5; c++) a = fmaf(oh[c], whB[k][c], a);
                nh[k] = ftanh_fast(a);
            }
#pragma unroll
            for (int k = 0; k < 5; k++) {
                oh[k] = __shfl_xor_sync(0xffffffffu, nh[k], 16);
                mh[k] = nh[k];
            }
        }
        // ---- step with xb ----
        {
            float nh[5];
#pragma unroll
            for (int k = 0; k < 5; k++) {
                float a = bias[k];
#pragma unroll
                for (int j = 0; j < 5; j++) a = fmaf(xb[j], wih[k][j], a);
#pragma unroll
                for (int c = 0; c < 5; c++) a = fmaf(mh[c], whA[k][c], a);
#pragma unroll
                for (int c = 0; c < 5; c++) a = fmaf(oh[c], whB[k][c], a);
                nh[k] = ftanh_fast(a);
            }
#pragma unroll
            for (int k = 0; k < 5; k++) {
                oh[k] = __shfl_xor_sync(0xffffffffu, nh[k], 16);
                mh[k] = nh[k];
            }
        }

#pragma unroll
        for (int j = 0; j < 5; j++) { xa[j] = xn0[j]; xb[j] = xn1[j]; }
    }

    // write my final units: y[b][dir*9 + u]
#pragma unroll
    for (int k = 0; k < 5; k++) {
        const int u = g * 5 + k;
        if (u < 9) g_y[b * 18 + dir * 9 + u] = mh[k];
    }
}

// ---------------------------------------------------------------------------
// Phase 2: 25-step RNN (H2=32) with input only at t=0, + 32->3 projection.
// One warp per batch element. Recurrence: shfl-broadcast GEMV; h_t history is
// staged in smem (stride 33 -> conflict-free) and projected once at the end
// (lane = timestep, 3 dots of length 32 each).
// ---------------------------------------------------------------------------
#define HS_STRIDE 33

__global__ __launch_bounds__(128) void rnn2_kernel(
    const float* __restrict__ wih2, const float* __restrict__ whh2,
    const float* __restrict__ bih2, const float* __restrict__ bhh2,
    const float* __restrict__ wout, const float* __restrict__ bout,
    float* __restrict__ out, int B)
{
    __shared__ float hs[4][25 * HS_STRIDE];

    const int warp = (blockIdx.x * blockDim.x + threadIdx.x) >> 5;
    const int wslot = (threadIdx.x >> 5) & 3;
    const int lane = threadIdx.x & 31;
    if (warp >= B) return;
    const int b = warp;

    // whh2 row for my unit, vectorized loads (row is 128B-aligned)
    float wh[32];
    {
        const float4* p = (const float4*)(whh2 + lane * 32);
#pragma unroll
        for (int q = 0; q < 8; q++) {
            float4 v = p[q];
            wh[q * 4 + 0] = v.x; wh[q * 4 + 1] = v.y;
            wh[q * 4 + 2] = v.z; wh[q * 4 + 3] = v.w;
        }
    }
    float wi[18];
#pragma unroll
    for (int j = 0; j < 18; j++) wi[j] = wih2[lane * 18 + j];
    const float bias = bih2[lane] + bhh2[lane];

    // t = 0: input is y; later steps input is zero.
    const float yv = (lane < 18) ? g_y[b * 18 + lane] : 0.f;
    float pre = bias;
#pragma unroll
    for (int j = 0; j < 18; j++)
        pre = fmaf(__shfl_sync(0xffffffffu, yv, j), wi[j], pre);
    float h = ftanh_exact(pre);
    hs[wslot][0 * HS_STRIDE + lane] = h;

#pragma unroll 4
    for (int t = 1; t < 25; t++) {
        float p = bias;
#pragma unroll
        for (int j = 0; j < 32; j++)
            p = fmaf(__shfl_sync(0xffffffffu, h, j), wh[j], p);
        h = ftanh_exact(p);
        hs[wslot][t * HS_STRIDE + lane] = h;
    }
    __syncwarp();

    // Projection: lane t computes out[b][t][0..2].
    if (lane < 25) {
        const int t = lane;
        float a0 = bout[0], a1 = bout[1], a2 = bout[2];
        const float* hrow = &hs[wslot][t * HS_STRIDE];
#pragma unroll
        for (int j = 0; j < 32; j++) {
            const float hv = hrow[j];
            a0 = fmaf(hv, wout[j],      a0);
            a1 = fmaf(hv, wout[32 + j], a1);
            a2 = fmaf(hv, wout[64 + j], a2);
        }
        float* ob = out + (long)b * 75 + t * 3;
        ob[0] = a0; ob[1] = a1; ob[2] = a2;
    }
}

extern "C" void kernel_launch(void* const* d_in, const int* in_sizes, int n_in,
                              void* d_out, int out_size)
{
    const float* x      = (const float*)d_in[0];
    const float* wih_f  = (const float*)d_in[1];
    const float* whh_f  = (const float*)d_in[2];
    const float* bih_f  = (const float*)d_in[3];
    const float* bhh_f  = (const float*)d_in[4];
    const float* wih_b  = (const float*)d_in[5];
    const float* whh_b  = (const float*)d_in[6];
    const float* bih_b  = (const float*)d_in[7];
    const float* bhh_b  = (const float*)d_in[8];
    const float* wih2   = (const float*)d_in[9];
    const float* whh2   = (const float*)d_in[10];
    const float* bih2   = (const float*)d_in[11];
    const float* bhh2   = (const float*)d_in[12];
    const float* wout   = (const float*)d_in[13];
    const float* bout   = (const float*)d_in[14];
    float* out = (float*)d_out;

    const int B = in_sizes[0] / (TLEN * 5);      // 4096
    const int warps1 = (2 * B) / 16;             // 512 warps
    rnn1_kernel<<<warps1 / 4, 128>>>(x, wih_f, whh_f, bih_f, bhh_f,
                                     wih_b, whh_b, bih_b, bhh_b);

    const int blocks2 = (B + 3) / 4;             // 4 warps per block
    rnn2_kernel<<<blocks2, 128>>>(wih2, whh2, bih2, bhh2, wout, bout, out, B);
}

// round 8
// speedup vs baseline: 1.1762x; 1.0860x over previous
#include <cuda_runtime.h>

#define TLEN 2048
#define NBMAX 4096

// Scratch for [h_f | h_b] per batch element: [B][18]
__device__ float g_y[NBMAX * 18];

// Fast HW tanh (MUFU.TANH). Saturates correctly for all finite inputs.
__device__ __forceinline__ float ftanh_fast(float x) {
    float y;
    asm("tanh.approx.f32 %0, %1;" : "=f"(y) : "f"(x));
    return y;
}

// Exact-ish tanh, clamp-free: 1 - 2/(e^{2x}+1).
__device__ __forceinline__ float ftanh_exact(float x) {
    float e = __expf(2.f * x);
    return fmaf(-2.f, __frcp_rn(e + 1.f), 1.f);
}

// Empty kernel: shifts ncu's launch-index parity so -s 5 -c 1 captures rnn1.
__global__ void parity_kernel() {}

// ---------------------------------------------------------------------------
// Phase 1: bidirectional Elman RNN (H1=9, D_IN=5), final hidden only.
// 3 lane-groups per sequence (3 units each: u=3g..3g+2), 8 seqs per warp
// (lanes 24..31 idle). 8 warps per block of 256 -> 2 warps per SMSP,
// 1024 warps total: stall holes of one warp are filled by the other.
// h-exchange: ring shfl with per-lane precomputed source lanes (6 shfl/step).
// Weights register-resident, columns permuted to arrival order (g, g+1, g+2).
// ---------------------------------------------------------------------------
__global__ __launch_bounds__(256) void rnn1_kernel(
    const float* __restrict__ x,
    const float* __restrict__ wih_f, const float* __restrict__ whh_f,
    const float* __restrict__ bih_f, const float* __restrict__ bhh_f,
    const float* __restrict__ wih_b, const float* __restrict__ whh_b,
    const float* __restrict__ bih_b, const float* __restrict__ bhh_b)
{
    const int lane = threadIdx.x & 31;
    const int g = lane >> 3;          // lane-group 0..3 (3 == idle)
    const int r = lane & 7;           // sequence slot within warp
    const int w = blockIdx.x * 8 + (threadIdx.x >> 5);   // global warp 0..1023
    const int wpd = 512;              // warps per direction (4096/8)
    const int dir = (w >= wpd) ? 1 : 0;
    const int b = (dir ? (w - wpd) : w) * 8 + r;
    const bool act = (g < 3);

    const float* Wih = dir ? wih_b : wih_f;
    const float* Whh = dir ? whh_b : whh_f;
    const float* Bi  = dir ? bih_b : bih_f;
    const float* Bh  = dir ? bhh_b : bhh_f;

    // ring-exchange source lanes (fixed for the whole loop)
    const int gp1 = (g + 1) % 3, gp2 = (g + 2) % 3;
    const int src1 = gp1 * 8 + r;
    const int src2 = gp2 * 8 + r;

    float wih[3][5];     // input weights for my 3 units
    float whh[3][9];     // Whh, columns permuted to hv arrival order
    float bias[3];

#pragma unroll
    for (int k = 0; k < 3; k++) {
        const int u = 3 * g + k;
#pragma unroll
        for (int j = 0; j < 5; j++)
            wih[k][j] = act ? Wih[u * 5 + j] : 0.f;
#pragma unroll
        for (int m = 0; m < 3; m++) {
            const int grp = (g + m) % 3;   // hv slots 3m..3m+2 hold group grp
#pragma unroll
            for (int j2 = 0; j2 < 3; j2++)
                whh[k][3 * m + j2] = act ? Whh[u * 9 + 3 * grp + j2] : 0.f;
        }
        bias[k] = act ? (Bi[u] + Bh[u]) : 0.f;
    }

    float hv[9];
#pragma unroll
    for (int s = 0; s < 9; s++) hv[s] = 0.f;

    const int stride = dir ? -5 : 5;
    const float* xp = x + ((long)b * TLEN + (dir ? (TLEN - 1) : 0)) * 5;

    float xa[5], xb[5];
#pragma unroll
    for (int j = 0; j < 5; j++) xa[j] = xp[j];
    xp += stride;
#pragma unroll
    for (int j = 0; j < 5; j++) xb[j] = xp[j];
    xp += stride;

    for (int t = 0; t < TLEN; t += 2) {
        // distance-2 prefetch (branchless: clamp the tail loads to a safe addr)
        float xn0[5], xn1[5];
        const float* p0 = (t + 2 < TLEN) ? xp : x;
        const float* p1 = (t + 3 < TLEN) ? (xp + stride) : x;
#pragma unroll
        for (int j = 0; j < 5; j++) xn0[j] = p0[j];
#pragma unroll
        for (int j = 0; j < 5; j++) xn1[j] = p1[j];
        xp += 2 * stride;

        // ---- step with xa ----
        {
            float a0 = bias[0], a1 = bias[1], a2 = bias[2];
#pragma unroll
            for (int j = 0; j < 5; j++) {
                a0 = fmaf(xa[j], wih[0][j], a0);
                a1 = fmaf(xa[j], wih[1][j], a1);
                a2 = fmaf(xa[j], wih[2][j], a2);
            }
#pragma unroll
            for (int s = 0; s < 9; s++) {
                a0 = fmaf(hv[s], whh[0][s], a0);
                a1 = fmaf(hv[s], whh[1][s], a1);
                a2 = fmaf(hv[s], whh[2][s], a2);
            }
            const float n0 = ftanh_fast(a0);
            const float n1 = ftanh_fast(a1);
            const float n2 = ftanh_fast(a2);
            hv[0] = n0; hv[1] = n1; hv[2] = n2;
            hv[3] = __shfl_sync(0xffffffffu, n0, src1);
            hv[4] = __shfl_sync(0xffffffffu, n1, src1);
            hv[5] = __shfl_sync(0xffffffffu, n2, src1);
            hv[6] = __shfl_sync(0xffffffffu, n0, src2);
            hv[7] = __shfl_sync(0xffffffffu, n1, src2);
            hv[8] = __shfl_sync(0xffffffffu, n2, src2);
        }
        // ---- step with xb ----
        {
            float a0 = bias[0], a1 = bias[1], a2 = bias[2];
#pragma unroll
            for (int j = 0; j < 5; j++) {
                a0 = fmaf(xb[j], wih[0][j], a0);
                a1 = fmaf(xb[j], wih[1][j], a1);
                a2 = fmaf(xb[j], wih[2][j], a2);
            }
#pragma unroll
            for (int s = 0; s < 9; s++) {
                a0 = fmaf(hv[s], whh[0][s], a0);
                a1 = fmaf(hv[s], whh[1][s], a1);
                a2 = fmaf(hv[s], whh[2][s], a2);
            }
            const float n0 = ftanh_fast(a0);
            const float n1 = ftanh_fast(a1);
            const float n2 = ftanh_fast(a2);
            hv[0] = n0; hv[1] = n1; hv[2] = n2;
            hv[3] = __shfl_sync(0xffffffffu, n0, src1);
            hv[4] = __shfl_sync(0xffffffffu, n1, src1);
            hv[5] = __shfl_sync(0xffffffffu, n2, src1);
            hv[6] = __shfl_sync(0xffffffffu, n0, src2);
            hv[7] = __shfl_sync(0xffffffffu, n1, src2);
            hv[8] = __shfl_sync(0xffffffffu, n2, src2);
        }

#pragma unroll
        for (int j = 0; j < 5; j++) { xa[j] = xn0[j]; xb[j] = xn1[j]; }
    }

    // write my final units: y[b][dir*9 + u]
    if (act) {
#pragma unroll
        for (int k = 0; k < 3; k++)
            g_y[b * 18 + dir * 9 + 3 * g + k] = hv[k];
    }
}

// ---------------------------------------------------------------------------
// Phase 2: 25-step RNN (H2=32) with input only at t=0, + 32->3 projection.
// One warp per batch element; shfl-broadcast GEMV; h history staged in smem
// (stride 33 -> conflict-free), single projection pass (lane = timestep).
// ---------------------------------------------------------------------------
#define HS_STRIDE 33

__global__ __launch_bounds__(128) void rnn2_kernel(
    const float* __restrict__ wih2, const float* __restrict__ whh2,
    const float* __restrict__ bih2, const float* __restrict__ bhh2,
    const float* __restrict__ wout, const float* __restrict__ bout,
    float* __restrict__ out, int B)
{
    __shared__ float hs[4][25 * HS_STRIDE];

    const int warp = (blockIdx.x * blockDim.x + threadIdx.x) >> 5;
    const int wslot = (threadIdx.x >> 5) & 3;
    const int lane = threadIdx.x & 31;
    if (warp >= B) return;
    const int b = warp;

    float wh[32];
    {
        const float4* p = (const float4*)(whh2 + lane * 32);
#pragma unroll
        for (int q = 0; q < 8; q++) {
            float4 v = p[q];
            wh[q * 4 + 0] = v.x; wh[q * 4 + 1] = v.y;
            wh[q * 4 + 2] = v.z; wh[q * 4 + 3] = v.w;
        }
    }
    float wi[18];
#pragma unroll
    for (int j = 0; j < 18; j++) wi[j] = wih2[lane * 18 + j];
    const float bias = bih2[lane] + bhh2[lane];

    // t = 0: input is y; later steps input is zero.
    const float yv = (lane < 18) ? g_y[b * 18 + lane] : 0.f;
    float pre = bias;
#pragma unroll
    for (int j = 0; j < 18; j++)
        pre = fmaf(__shfl_sync(0xffffffffu, yv, j), wi[j], pre);
    float h = ftanh_exact(pre);
    hs[wslot][0 * HS_STRIDE + lane] = h;

#pragma unroll 4
    for (int t = 1; t < 25; t++) {
        float p = bias;
#pragma unroll
        for (int j = 0; j < 32; j++)
            p = fmaf(__shfl_sync(0xffffffffu, h, j), wh[j], p);
        h = ftanh_exact(p);
        hs[wslot][t * HS_STRIDE + lane] = h;
    }
    __syncwarp();

    // Projection: lane t computes out[b][t][0..2].
    if (lane < 25) {
        const int t = lane;
        float a0 = bout[0], a1 = bout[1], a2 = bout[2];
        const float* hrow = &hs[wslot][t * HS_STRIDE];
#pragma unroll
        for (int j = 0; j < 32; j++) {
            const float hvv = hrow[j];
            a0 = fmaf(hvv, wout[j],      a0);
            a1 = fmaf(hvv, wout[32 + j], a1);
            a2 = fmaf(hvv, wout[64 + j], a2);
        }
        float* ob = out + (long)b * 75 + t * 3;
        ob[0] = a0; ob[1] = a1; ob[2] = a2;
    }
}

extern "C" void kernel_launch(void* const* d_in, const int* in_sizes, int n_in,
                              void* d_out, int out_size)
{
    const float* x      = (const float*)d_in[0];
    const float* wih_f  = (const float*)d_in[1];
    const float* whh_f  = (const float*)d_in[2];
    const float* bih_f  = (const float*)d_in[3];
    const float* bhh_f  = (const float*)d_in[4];
    const float* wih_b  = (const float*)d_in[5];
    const float* whh_b  = (const float*)d_in[6];
    const float* bih_b  = (const float*)d_in[7];
    const float* bhh_b  = (const float*)d_in[8];
    const float* wih2   = (const float*)d_in[9];
    const float* whh2   = (const float*)d_in[10];
    const float* bih2   = (const float*)d_in[11];
    const float* bhh2   = (const float*)d_in[12];
    const float* wout   = (const float*)d_in[13];
    const float* bout   = (const float*)d_in[14];
    float* out = (float*)d_out;

    const int B = in_sizes[0] / (TLEN * 5);      // 4096

    // 4 launches per call -> ncu (-s 5 -c 1) lands on rnn1 (index 5 mod 4 == 1).
    parity_kernel<<<1, 32>>>();

    const int warps1 = (2 * B) / 8;              // 1024 warps
    rnn1_kernel<<<warps1 / 8, 256>>>(x, wih_f, whh_f, bih_f, bhh_f,
                                     wih_b, whh_b, bih_b, bhh_b);

    const int blocks2 = (B + 3) / 4;             // 4 warps per block
    rnn2_kernel<<<blocks2, 128>>>(wih2, whh2, bih2, bhh2, wout, bout, out, B);

    parity_kernel<<<1, 32>>>();
}

// round 10
// speedup vs baseline: 1.9024x; 1.6175x over previous
#include <cuda_runtime.h>

#define TLEN   2048
#define CSTEP  16
#define NCHUNK (TLEN / CSTEP)      // 128
#define XSTRIDE 132                // floats per seq chunk block: 16*8 + 4 pad
#define SEQB   32                  // sequences per block

// Fast HW tanh (MUFU.TANH).
__device__ __forceinline__ float ftanh_fast(float x) {
    float y;
    asm("tanh.approx.f32 %0, %1;" : "=f"(y) : "f"(x));
    return y;
}
// Exact-ish tanh for phase 2.
__device__ __forceinline__ float ftanh_exact(float x) {
    float e = __expf(2.f * x);
    return fmaf(-2.f, __frcp_rn(e + 1.f), 1.f);
}

// ---------------------------------------------------------------------------
// Single fused kernel.
// Phase 1: block = 8 warps; warps 0-3 forward, 4-7 backward, same 32 seqs.
//   Per warp: 8 seqs, 3 lane-groups of 3 hidden units (lanes 24-31 idle).
//   x staged through smem in 16-step chunks; global->reg prefetch for chunk
//   c+1 issued before computing chunk c (DRAM latency hidden by compute).
//   smem rows are stored in NATURAL time order (row = trow) for both
//   directions; the backward warps walk rows 15 -> 0 (single source of truth
//   for time reversal -- the R8 bug was reversing in BOTH places).
// Phase 2: 25-step H2=32 RNN + 32->3 projection, fused, 4 seqs per warp.
// ---------------------------------------------------------------------------
__global__ __launch_bounds__(256) void birnn_kernel(
    const float* __restrict__ x,
    const float* __restrict__ wih_f, const float* __restrict__ whh_f,
    const float* __restrict__ bih_f, const float* __restrict__ bhh_f,
    const float* __restrict__ wih_b, const float* __restrict__ whh_b,
    const float* __restrict__ bih_b, const float* __restrict__ bhh_b,
    const float* __restrict__ wih2, const float* __restrict__ whh2,
    const float* __restrict__ bih2, const float* __restrict__ bhh2,
    const float* __restrict__ wout, const float* __restrict__ bout,
    float* __restrict__ out)
{
    __shared__ __align__(16) float xs[2 * SEQB * XSTRIDE];   // 33,792 B
    __shared__ float ys[SEQB * 19];                          // phase1 -> phase2

    const int tid  = threadIdx.x;
    const int warp = tid >> 5;          // 0..7
    const int lane = tid & 31;
    const int isB  = warp >> 2;         // 0 fwd, 1 bwd
    const int wq   = warp & 3;
    const int g    = lane >> 3;         // unit-group 0..2 (3 = idle)
    const int r    = lane & 7;          // seq slot within warp
    const int s_loc = wq * 8 + r;       // block-local seq 0..31
    const bool act = (g < 3);

    const float* Wih = isB ? wih_b : wih_f;
    const float* Whh = isB ? whh_b : whh_f;
    const float* Bi  = isB ? bih_b : bih_f;
    const float* Bh  = isB ? bhh_b : bhh_f;

    // ring-exchange source lanes
    const int gp1 = (g + 1) % 3, gp2 = (g + 2) % 3;
    const int src1 = gp1 * 8 + r;
    const int src2 = gp2 * 8 + r;

    float wih[3][5], whh[3][9], bias[3];
#pragma unroll
    for (int k = 0; k < 3; k++) {
        const int u = 3 * g + k;
#pragma unroll
        for (int j = 0; j < 5; j++)
            wih[k][j] = act ? Wih[u * 5 + j] : 0.f;
#pragma unroll
        for (int m = 0; m < 3; m++) {
            const int grp = (g + m) % 3;
#pragma unroll
            for (int j2 = 0; j2 < 3; j2++)
                whh[k][3 * m + j2] = act ? Whh[u * 9 + 3 * grp + j2] : 0.f;
        }
        bias[k] = act ? (Bi[u] + Bh[u]) : 0.f;
    }

    float hv[9];
#pragma unroll
    for (int s = 0; s < 9; s++) hv[s] = 0.f;

    // -------- staged x prefetch: 1280 float4 per chunk-pair, 5 per thread ----
    // fwd buffer (buf=0): chunk c = steps 16c..16c+15   (float4 base 20c)
    // bwd buffer (buf=1): chunk c = steps 2032-16c..2047-16c (f4 base 2540-20c)
    float4 st[5];
    auto loadStage = [&](int cn) {
        const int valid = (cn < NCHUNK);
        const int t4f = valid ? 20 * cn : 0;
        const int t4b = valid ? (2540 - 20 * cn) : 2540;
#pragma unroll
        for (int it = 0; it < 5; it++) {
            const int idx = tid + it * 256;             // 0..1279
            const int buf = (idx >= 640);
            const int rem = idx - buf * 640;
            const int s   = rem / 20;
            const int k   = rem - s * 20;
            const int bg  = blockIdx.x * SEQB + s;
            const int f4i = bg * 2560 + (buf ? t4b : t4f) + k;
            st[it] = __ldg((const float4*)x + f4i);
        }
    };
    auto storeStage = [&]() {
#pragma unroll
        for (int it = 0; it < 5; it++) {
            const int idx = tid + it * 256;
            const int buf = (idx >= 640);
            const int rem = idx - buf * 640;
            const int s   = rem / 20;
            const int k   = rem - s * 20;
            float v[4] = { st[it].x, st[it].y, st[it].z, st[it].w };
#pragma unroll
            for (int jj = 0; jj < 4; jj++) {
                const int f = 4 * k + jj;               // 0..79
                const int trow = f / 5;                 // local time 0..15
                const int j = f - 5 * trow;
                // natural time order for BOTH directions (fix of R8 bug)
                xs[buf * (SEQB * XSTRIDE) + s * XSTRIDE + trow * 8 + j] = v[jj];
            }
        }
    };

    // backward warps walk rows 15 -> 0 (this is the ONLY time reversal)
    const float* xp0 = xs + isB * (SEQB * XSTRIDE) + s_loc * XSTRIDE + (isB ? 120 : 0);
    const int dstep = isB ? -8 : 8;

    loadStage(0);
    for (int c = 0; c < NCHUNK; c++) {
        storeStage();
        __syncthreads();
        loadStage(c + 1);           // hidden under the 16-step compute below

        const float* p = xp0;
#pragma unroll
        for (int i = 0; i < CSTEP; i++) {
            const float4 xv = *(const float4*)p;
            const float  x4 = p[4];
            p += dstep;

            float a0 = bias[0], a1 = bias[1], a2 = bias[2];
            a0 = fmaf(xv.x, wih[0][0], a0); a1 = fmaf(xv.x, wih[1][0], a1); a2 = fmaf(xv.x, wih[2][0], a2);
            a0 = fmaf(xv.y, wih[0][1], a0); a1 = fmaf(xv.y, wih[1][1], a1); a2 = fmaf(xv.y, wih[2][1], a2);
            a0 = fmaf(xv.z, wih[0][2], a0); a1 = fmaf(xv.z, wih[1][2], a1); a2 = fmaf(xv.z, wih[2][2], a2);
            a0 = fmaf(xv.w, wih[0][3], a0); a1 = fmaf(xv.w, wih[1][3], a1); a2 = fmaf(xv.w, wih[2][3], a2);
            a0 = fmaf(x4,   wih[0][4], a0); a1 = fmaf(x4,   wih[1][4], a1); a2 = fmaf(x4,   wih[2][4], a2);
#pragma unroll
            for (int s = 0; s < 9; s++) {
                a0 = fmaf(hv[s], whh[0][s], a0);
                a1 = fmaf(hv[s], whh[1][s], a1);
                a2 = fmaf(hv[s], whh[2][s], a2);
            }
            const float n0 = ftanh_fast(a0);
            const float n1 = ftanh_fast(a1);
            const float n2 = ftanh_fast(a2);
            hv[0] = n0; hv[1] = n1; hv[2] = n2;
            hv[3] = __shfl_sync(0xffffffffu, n0, src1);
            hv[4] = __shfl_sync(0xffffffffu, n1, src1);
            hv[5] = __shfl_sync(0xffffffffu, n2, src1);
            hv[6] = __shfl_sync(0xffffffffu, n0, src2);
            hv[7] = __shfl_sync(0xffffffffu, n1, src2);
            hv[8] = __shfl_sync(0xffffffffu, n2, src2);
        }
        __syncthreads();
    }

    // final hidden -> ys[s][dir*9 + u]
    if (act) {
#pragma unroll
        for (int k = 0; k < 3; k++)
            ys[s_loc * 19 + isB * 9 + 3 * g + k] = hv[k];
    }
    __syncthreads();

    // ---------------- Phase 2: each warp handles 4 batch elements ----------
    float wh[32];
    {
        const float4* pw = (const float4*)(whh2 + lane * 32);
#pragma unroll
        for (int q = 0; q < 8; q++) {
            float4 v = pw[q];
            wh[q * 4 + 0] = v.x; wh[q * 4 + 1] = v.y;
            wh[q * 4 + 2] = v.z; wh[q * 4 + 3] = v.w;
        }
    }
    float wi[18];
#pragma unroll
    for (int j = 0; j < 18; j++) wi[j] = wih2[lane * 18 + j];
    const float bias2 = bih2[lane] + bhh2[lane];
    const float bo0 = bout[0], bo1 = bout[1], bo2 = bout[2];

    float* hsbuf = xs + warp * 825;     // reuse xs: 8 warps x 25*33 floats

    for (int q = 0; q < 4; q++) {
        const int bl = warp * 4 + q;
        const long bg = (long)blockIdx.x * SEQB + bl;

        const float yv = (lane < 18) ? ys[bl * 19 + lane] : 0.f;
        float pre = bias2;
#pragma unroll
        for (int j = 0; j < 18; j++)
            pre = fmaf(__shfl_sync(0xffffffffu, yv, j), wi[j], pre);
        float h = ftanh_exact(pre);
        hsbuf[0 * 33 + lane] = h;

#pragma unroll 4
        for (int t = 1; t < 25; t++) {
            float p = bias2;
#pragma unroll
            for (int j = 0; j < 32; j++)
                p = fmaf(__shfl_sync(0xffffffffu, h, j), wh[j], p);
            h = ftanh_exact(p);
            hsbuf[t * 33 + lane] = h;
        }
        __syncwarp();

        if (lane < 25) {
            float a0 = bo0, a1 = bo1, a2 = bo2;
            const float* hrow = hsbuf + lane * 33;
#pragma unroll
            for (int j = 0; j < 32; j++) {
                const float hvv = hrow[j];
                a0 = fmaf(hvv, wout[j],      a0);
                a1 = fmaf(hvv, wout[32 + j], a1);
                a2 = fmaf(hvv, wout[64 + j], a2);
            }
            float* ob = out + bg * 75 + lane * 3;
            ob[0] = a0; ob[1] = a1; ob[2] = a2;
        }
        __syncwarp();
    }
}

extern "C" void kernel_launch(void* const* d_in, const int* in_sizes, int n_in,
                              void* d_out, int out_size)
{
    const float* x      = (const float*)d_in[0];
    const float* wih_f  = (const float*)d_in[1];
    const float* whh_f  = (const float*)d_in[2];
    const float* bih_f  = (const float*)d_in[3];
    const float* bhh_f  = (const float*)d_in[4];
    const float* wih_b  = (const float*)d_in[5];
    const float* whh_b  = (const float*)d_in[6];
    const float* bih_b  = (const float*)d_in[7];
    const float* bhh_b  = (const float*)d_in[8];
    const float* wih2   = (const float*)d_in[9];
    const float* whh2   = (const float*)d_in[10];
    const float* bih2   = (const float*)d_in[11];
    const float* bhh2   = (const float*)d_in[12];
    const float* wout   = (const float*)d_in[13];
    const float* bout   = (const float*)d_in[14];
    float* out = (float*)d_out;

    const int B = in_sizes[0] / (TLEN * 5);      // 4096
    birnn_kernel<<<B / SEQB, 256>>>(x,
        wih_f, whh_f, bih_f, bhh_f,
        wih_b, whh_b, bih_b, bhh_b,
        wih2, whh2, bih2, bhh2, wout, bout, out);
}